// round 1
// baseline (speedup 1.0000x reference)
#include <cuda_runtime.h>
#include <cuda_bf16.h>
#include <mma.h>

using namespace nvcuda;

// Problem constants (shapes fixed by setup_inputs)
#define NMAX 200000
#define D 128
#define LDA 136  // padded smem leading dim (floats)

static const int SMEM_BYTES = 3 * 128 * LDA * 4;  // hA + Wbuf + rS = 204KB

// Scratch (static device globals: allocation is forbidden)
__device__ float g_h[(size_t)NMAX * D];
__device__ float g_z[NMAX];
__device__ float g_deg[NMAX];
__device__ float g_dis[NMAX];
__device__ float g_u[NMAX];
__device__ float g_t[NMAX];

// ---------------------------------------------------------------------------
// h = relu(x @ Win^T + b_in)
__global__ void k_input(const float* __restrict__ x, const float* __restrict__ Win,
                        const float* __restrict__ b_in, int N) {
    int idx = blockIdx.x * blockDim.x + threadIdx.x;
    if (idx >= N * D) return;
    int n = idx >> 7, d = idx & 127;
    float v = b_in[d] + x[n * 3 + 0] * Win[d * 3 + 0]
                      + x[n * 3 + 1] * Win[d * 3 + 1]
                      + x[n * 3 + 2] * Win[d * 3 + 2];
    g_h[idx] = fmaxf(v, 0.f);
}

// ---------------------------------------------------------------------------
// Fused: h = LN( h + Wb @ act(Wa @ h + ba) + bb )   (tf32 wmma, fp32 accum)
// Wa: [F, 128] row-major, Wb: [128, F] row-major. F multiple of 128.
__global__ __launch_bounds__(256, 1)
void fused_layer_kernel(const float* __restrict__ Wa, const float* __restrict__ ba,
                        const float* __restrict__ Wb, const float* __restrict__ bb,
                        const float* __restrict__ lng, const float* __restrict__ lnb,
                        int F, int relu_mid, int N) {
    extern __shared__ float smem[];
    float* hA   = smem;                 // [128][LDA] input tile (tf32)
    float* Wbuf = smem + 128 * LDA;     // [128][LDA] weight chunk (tf32)
    float* rS   = smem + 2 * 128 * LDA; // [128][LDA] mid activations / out

    const int tid  = threadIdx.x;
    const int w    = tid >> 5;
    const int lane = tid & 31;
    const int row0 = blockIdx.x * 128;

    // Prologue: stage input rows (zero-pad past N)
    for (int idx = tid; idx < 128 * 128; idx += 256) {
        int r = idx >> 7, c = idx & 127;
        int gr = row0 + r;
        float v = (gr < N) ? g_h[(size_t)gr * D + c] : 0.f;
        hA[r * LDA + c] = wmma::__float_to_tf32(v);
    }

    wmma::fragment<wmma::accumulator, 16, 16, 8, float> acc[8];
#pragma unroll
    for (int j = 0; j < 8; j++) wmma::fill_fragment(acc[j], 0.f);

    const int nchunk = F >> 7;
    for (int ch = 0; ch < nchunk; ch++) {
        const int f0 = ch << 7;
        __syncthreads();  // previous iter done with Wbuf/rS
        // Load Wa chunk: Wbuf[f][d] = Wa[f0+f][d]  (B col-major, k=d, n=f)
        for (int idx = tid; idx < 128 * 128; idx += 256) {
            int f = idx >> 7, d = idx & 127;
            Wbuf[f * LDA + d] = wmma::__float_to_tf32(Wa[(size_t)(f0 + f) * D + d]);
        }
        __syncthreads();
        // Stage 1: r[16,128] = hA_warp @ WaChunk^T  (two halves to cap registers)
#pragma unroll
        for (int half = 0; half < 2; half++) {
            wmma::fragment<wmma::accumulator, 16, 16, 8, float> rf[4];
#pragma unroll
            for (int j = 0; j < 4; j++) wmma::fill_fragment(rf[j], 0.f);
#pragma unroll
            for (int kk = 0; kk < 16; kk++) {
                wmma::fragment<wmma::matrix_a, 16, 16, 8, wmma::precision::tf32, wmma::row_major> aF;
                wmma::load_matrix_sync(aF, hA + (w * 16) * LDA + kk * 8, LDA);
#pragma unroll
                for (int j = 0; j < 4; j++) {
                    wmma::fragment<wmma::matrix_b, 16, 16, 8, wmma::precision::tf32, wmma::col_major> bF;
                    wmma::load_matrix_sync(bF, Wbuf + (half * 64 + j * 16) * LDA + kk * 8, LDA);
                    wmma::mma_sync(rf[j], aF, bF, rf[j]);
                }
            }
#pragma unroll
            for (int j = 0; j < 4; j++)
                wmma::store_matrix_sync(rS + (w * 16) * LDA + half * 64 + j * 16, rf[j],
                                        LDA, wmma::mem_row_major);
        }
        __syncwarp();
        // bias + optional relu + tf32-truncate, warp-private rows
        for (int t = lane; t < 16 * 128; t += 32) {
            int r = t >> 7, c = t & 127;
            float v = rS[(w * 16 + r) * LDA + c] + ba[f0 + c];
            if (relu_mid) v = fmaxf(v, 0.f);
            rS[(w * 16 + r) * LDA + c] = wmma::__float_to_tf32(v);
        }
        __syncthreads();
        // Load Wb chunk: Wbuf[d2][f] = Wb[d2][f0+f]  (B col-major, k=f, n=d2)
        for (int idx = tid; idx < 128 * 128; idx += 256) {
            int d2 = idx >> 7, f = idx & 127;
            Wbuf[d2 * LDA + f] = wmma::__float_to_tf32(Wb[(size_t)d2 * F + f0 + f]);
        }
        __syncthreads();
        // Stage 2: acc += r @ WbChunk^T
#pragma unroll
        for (int kk = 0; kk < 16; kk++) {
            wmma::fragment<wmma::matrix_a, 16, 16, 8, wmma::precision::tf32, wmma::row_major> aF;
            wmma::load_matrix_sync(aF, rS + (w * 16) * LDA + kk * 8, LDA);
#pragma unroll
            for (int j = 0; j < 8; j++) {
                wmma::fragment<wmma::matrix_b, 16, 16, 8, wmma::precision::tf32, wmma::col_major> bF;
                wmma::load_matrix_sync(bF, Wbuf + (j * 16) * LDA + kk * 8, LDA);
                wmma::mma_sync(acc[j], aF, bF, acc[j]);
            }
        }
    }
    __syncthreads();
#pragma unroll
    for (int j = 0; j < 8; j++)
        wmma::store_matrix_sync(rS + (w * 16) * LDA + j * 16, acc[j], LDA, wmma::mem_row_major);
    __syncwarp();

    // Epilogue: residual + bias + LayerNorm, one warp per 16 rows
    for (int r = 0; r < 16; r++) {
        int gr = row0 + w * 16 + r;
        if (gr >= N) break;
        float vals[4];
        float s = 0.f, sq = 0.f;
#pragma unroll
        for (int q = 0; q < 4; q++) {
            int c = lane + q * 32;
            float ff  = rS[(w * 16 + r) * LDA + c] + bb[c];
            float res = g_h[(size_t)gr * D + c];
            float v = res + ff;
            vals[q] = v;
            s += v; sq += v * v;
        }
#pragma unroll
        for (int o = 16; o; o >>= 1) {
            s  += __shfl_xor_sync(0xffffffffu, s, o);
            sq += __shfl_xor_sync(0xffffffffu, sq, o);
        }
        float m   = s * (1.f / 128.f);
        float var = sq * (1.f / 128.f) - m * m;
        float inv = rsqrtf(var + 1e-5f);
#pragma unroll
        for (int q = 0; q < 4; q++) {
            int c = lane + q * 32;
            g_h[(size_t)gr * D + c] = (vals[q] - m) * inv * lng[c] + lnb[c];
        }
    }
}

// ---------------------------------------------------------------------------
// z = relu(h @ Wd^T + bd) : one warp per row
__global__ void k_head(const float* __restrict__ Wd, const float* __restrict__ bd, int N) {
    int warp = (blockIdx.x * blockDim.x + threadIdx.x) >> 5;
    int lane = threadIdx.x & 31;
    if (warp >= N) return;
    float s = 0.f;
#pragma unroll
    for (int q = 0; q < 4; q++) {
        int c = lane + q * 32;
        s += g_h[(size_t)warp * D + c] * Wd[c];
    }
#pragma unroll
    for (int o = 16; o; o >>= 1) s += __shfl_xor_sync(0xffffffffu, s, o);
    if (lane == 0) g_z[warp] = fmaxf(s + bd[0], 0.f);
}

__global__ void k_deg_init(int N) {
    int n = blockIdx.x * blockDim.x + threadIdx.x;
    if (n < N) g_deg[n] = 1.0f;  // self-loop
}

__global__ void k_deg_count(const int* __restrict__ col, int E) {
    int e = blockIdx.x * blockDim.x + threadIdx.x;
    if (e < E) atomicAdd(&g_deg[col[e]], 1.0f);
}

__global__ void k_dis_u(int N) {
    int n = blockIdx.x * blockDim.x + threadIdx.x;
    if (n >= N) return;
    float dis = rsqrtf(fmaxf(g_deg[n], 1.0f));
    float u = g_z[n] * dis;
    g_dis[n] = dis;
    g_u[n] = u;
    g_t[n] = u;  // self-loop term: s = dis*(sum_u + u_self) = dis*sum + z*dis^2
}

__global__ void k_scatter(const int* __restrict__ row, const int* __restrict__ col, int E) {
    int e = blockIdx.x * blockDim.x + threadIdx.x;
    if (e < E) atomicAdd(&g_t[col[e]], g_u[row[e]]);
}

// out[n] = sum_k relu(s*Wg[k]+bg[k])*Wf[k] + bf ; s = dis[n]*t[n]
__global__ void k_out(const float* __restrict__ Wg, const float* __restrict__ bg,
                      const float* __restrict__ Wf, const float* __restrict__ bf,
                      float* __restrict__ out, int N) {
    int n = blockIdx.x * blockDim.x + threadIdx.x;
    if (n >= N) return;
    float s = g_dis[n] * g_t[n];
    float a = bf[0];
#pragma unroll
    for (int k = 0; k < 32; k++)
        a += fmaxf(s * Wg[k] + bg[k], 0.f) * Wf[k];
    out[n] = a;
}

// ---------------------------------------------------------------------------
extern "C" void kernel_launch(void* const* d_in, const int* in_sizes, int n_in,
                              void* d_out, int out_size) {
    const float* x    = (const float*)d_in[0];
    const int*   edge = (const int*)  d_in[1];
    const float* Win  = (const float*)d_in[2];
    const float* b_in = (const float*)d_in[3];
    const float* Wv   = (const float*)d_in[4];
    const float* bv   = (const float*)d_in[5];
    const float* Wo   = (const float*)d_in[6];
    const float* bo   = (const float*)d_in[7];
    const float* W1   = (const float*)d_in[8];
    const float* b1   = (const float*)d_in[9];
    const float* W2   = (const float*)d_in[10];
    const float* b2   = (const float*)d_in[11];
    const float* ln1g = (const float*)d_in[12];
    const float* ln1b = (const float*)d_in[13];
    const float* ln2g = (const float*)d_in[14];
    const float* ln2b = (const float*)d_in[15];
    const float* Wd   = (const float*)d_in[16];
    const float* bd   = (const float*)d_in[17];
    const float* Wg   = (const float*)d_in[18];
    const float* bg   = (const float*)d_in[19];
    const float* Wf   = (const float*)d_in[20];
    const float* bf   = (const float*)d_in[21];

    const int N = in_sizes[0] / 3;
    const int E = in_sizes[1] / 2;
    const int F = 2048;

    cudaFuncSetAttribute(fused_layer_kernel,
                         cudaFuncAttributeMaxDynamicSharedMemorySize, SMEM_BYTES);

    k_input<<<(N * D + 255) / 256, 256>>>(x, Win, b_in, N);

    const int blocks = (N + 127) / 128;
    for (int i = 0; i < 3; i++) {
        fused_layer_kernel<<<blocks, 256, SMEM_BYTES>>>(
            Wv + (size_t)i * D * D, bv + i * D, Wo + (size_t)i * D * D, bo + i * D,
            ln1g + i * D, ln1b + i * D, /*F=*/D, /*relu_mid=*/0, N);
        fused_layer_kernel<<<blocks, 256, SMEM_BYTES>>>(
            W1 + (size_t)i * F * D, b1 + i * F, W2 + (size_t)i * D * F, b2 + i * D,
            ln2g + i * D, ln2b + i * D, /*F=*/F, /*relu_mid=*/1, N);
    }

    k_head<<<(N + 7) / 8, 256>>>(Wd, bd, N);
    k_deg_init<<<(N + 255) / 256, 256>>>(N);
    k_deg_count<<<(E + 255) / 256, 256>>>(edge + E, E);
    k_dis_u<<<(N + 255) / 256, 256>>>(N);
    k_scatter<<<(E + 255) / 256, 256>>>(edge, edge + E, E);
    k_out<<<(N + 255) / 256, 256>>>(Wg, bg, Wf, bf, (float*)d_out, N);
}

// round 3
// speedup vs baseline: 3.0276x; 3.0276x over previous
#include <cuda_runtime.h>
#include <cuda_bf16.h>
#include <mma.h>
#include <cstdint>

using namespace nvcuda;

#define NMAX 200000
#define D 128
#define LDH 132      // hA / Wa-chunk leading dim (floats)
#define LDR 68       // rS / Wb-chunk leading dim (floats)
#define CHUNK 64
#define BUF_FLOATS 8704   // max(64*LDH=8448, 128*LDR=8704)

static const int SMEM_BYTES = (128 * LDH + 128 * LDR + 3 * BUF_FLOATS) * 4;  // 206848 B

// Scratch (static device globals: allocation is forbidden)
__device__ float g_h[(size_t)NMAX * D];
__device__ float g_z[NMAX];
__device__ float g_deg[NMAX];
__device__ float g_dis[NMAX];
__device__ float g_u[NMAX];
__device__ float g_t[NMAX];
// tf32-RN pre-converted weights: [Wv 3x16384 | Wo 3x16384 | W1 3x262144 | W2 3x262144]
__device__ float g_wcvt[1671168];

// ---------------------------------------------------------------------------
__device__ __forceinline__ void cp16(float* dst_smem, const float* src) {
    unsigned int d = (unsigned int)__cvta_generic_to_shared(dst_smem);
    asm volatile("cp.async.cg.shared.global [%0], [%1], 16;\n" :: "r"(d), "l"(src));
}
__device__ __forceinline__ void cp_commit() { asm volatile("cp.async.commit_group;\n"); }
template <int NPEND>
__device__ __forceinline__ void cp_wait() { asm volatile("cp.async.wait_group %0;\n" :: "n"(NPEND)); }

// ---------------------------------------------------------------------------
__global__ void k_cvt(const float* __restrict__ src, float* __restrict__ dst, int n) {
    int i = blockIdx.x * blockDim.x + threadIdx.x;
    if (i < n) dst[i] = wmma::__float_to_tf32(src[i]);
}

// h = relu(x @ Win^T + b_in)
__global__ void k_input(const float* __restrict__ x, const float* __restrict__ Win,
                        const float* __restrict__ b_in, int N) {
    int idx = blockIdx.x * blockDim.x + threadIdx.x;
    if (idx >= N * D) return;
    int n = idx >> 7, d = idx & 127;
    float v = b_in[d] + x[n * 3 + 0] * Win[d * 3 + 0]
                      + x[n * 3 + 1] * Win[d * 3 + 1]
                      + x[n * 3 + 2] * Win[d * 3 + 2];
    g_h[idx] = fmaxf(v, 0.f);
}

// ---------------------------------------------------------------------------
// Fused: h = LN( h + Wb @ act(Wa @ h + ba) + bb )   (tf32 wmma, fp32 accum)
// Wa: [F,128] row-major (tf32), Wb: [128,F] row-major (tf32). F % 64 == 0.
// 512 threads = 16 warps: warp w -> row tile wr=w>>1 (16 rows), col half wc=w&1.
__global__ __launch_bounds__(512, 1)
void fused_layer_kernel(const float* __restrict__ Wa, const float* __restrict__ ba,
                        const float* __restrict__ Wb, const float* __restrict__ bb,
                        const float* __restrict__ lng, const float* __restrict__ lnb,
                        int F, int relu_mid, int N) {
    extern __shared__ float smem[];
    float* hA  = smem;                       // [128][LDH]
    float* rS  = smem + 128 * LDH;           // [128][LDR]
    float* WBF = rS + 128 * LDR;             // 3 x BUF_FLOATS ring

    const int tid  = threadIdx.x;
    const int w    = tid >> 5;
    const int lane = tid & 31;
    const int wr   = w >> 1;
    const int wc   = w & 1;
    const int r0   = wr * 16;
    const int row0 = blockIdx.x * 128;
    const int nch  = F >> 6;

    // Prefetch chunk 0 weights into ring slots 0 (Wa) and 1 (Wb)
    {
        float* buf = WBF;  // slot 0: Wa[0]: [64 rows f][128 d]
        for (int i = tid; i < 64 * 32; i += 512) {
            int f = i >> 5, s = i & 31;
            cp16(buf + f * LDH + s * 4, Wa + (size_t)f * D + s * 4);
        }
        cp_commit();
        buf = WBF + BUF_FLOATS;  // slot 1: Wb[0]: [128 rows d2][64 f]
        for (int i = tid; i < 128 * 16; i += 512) {
            int d2 = i >> 4, s = i & 15;
            cp16(buf + d2 * LDR + s * 4, Wb + (size_t)d2 * F + s * 4);
        }
        cp_commit();
    }

    // Stage input rows (tf32-RN) while copies fly
    for (int i = tid; i < 128 * 128; i += 512) {
        int r = i >> 7, c = i & 127;
        int gr = row0 + r;
        float v = (gr < N) ? g_h[(size_t)gr * D + c] : 0.f;
        hA[r * LDH + c] = wmma::__float_to_tf32(v);
    }

    wmma::fragment<wmma::accumulator, 16, 16, 8, float> acc[4];
#pragma unroll
    for (int j = 0; j < 4; j++) wmma::fill_fragment(acc[j], 0.f);

    int ia = 0;  // ring slot of Wa[ch]; Wb[ch] is slot ia+1 (mod 3)
    for (int ch = 0; ch < nch; ch++) {
        const int f0 = ch << 6;
        int ib = ia + 1; if (ib == 3) ib = 0;
        int in = ib + 1; if (in == 3) in = 0;      // slot for Wa[ch+1]
        float* bufA = WBF + ia * BUF_FLOATS;
        float* bufB = WBF + ib * BUF_FLOATS;

        cp_wait<1>();          // Wa[ch] landed (Wb[ch] may still be pending)
        __syncthreads();       // visibility + hA ready (ch 0) + rS free (prev stage2 done)

        if (ch + 1 < nch) {    // prefetch Wa[ch+1] into freed slot
            float* nb = WBF + in * BUF_FLOATS;
            const float* src = Wa + (size_t)(f0 + 64) * D;
            for (int i = tid; i < 64 * 32; i += 512) {
                int f = i >> 5, s = i & 31;
                cp16(nb + f * LDH + s * 4, src + (size_t)f * D + s * 4);
            }
            cp_commit();
        }

        // Stage 1: rS[r0:+16, wc*32:+32] = hA_rows @ WaChunk^T
        {
            wmma::fragment<wmma::accumulator, 16, 16, 8, float> rf[2];
#pragma unroll
            for (int j = 0; j < 2; j++) wmma::fill_fragment(rf[j], 0.f);
#pragma unroll
            for (int kk = 0; kk < 16; kk++) {
                wmma::fragment<wmma::matrix_a, 16, 16, 8, wmma::precision::tf32, wmma::row_major> aF;
                wmma::load_matrix_sync(aF, hA + r0 * LDH + kk * 8, LDH);
#pragma unroll
                for (int j = 0; j < 2; j++) {
                    wmma::fragment<wmma::matrix_b, 16, 16, 8, wmma::precision::tf32, wmma::col_major> bF;
                    wmma::load_matrix_sync(bF, bufA + (wc * 32 + j * 16) * LDH + kk * 8, LDH);
                    wmma::mma_sync(rf[j], aF, bF, rf[j]);
                }
            }
#pragma unroll
            for (int j = 0; j < 2; j++)
                wmma::store_matrix_sync(rS + r0 * LDR + wc * 32 + j * 16, rf[j], LDR,
                                        wmma::mem_row_major);
        }
        __syncwarp();
        // bias + optional relu + tf32-RN, warp-private region (16 rows x 32 cols)
        for (int t = lane; t < 16 * 32; t += 32) {
            int rr = t >> 5, cc = t & 31;
            float* p = rS + (r0 + rr) * LDR + wc * 32 + cc;
            float v = *p + ba[f0 + wc * 32 + cc];
            if (relu_mid) v = fmaxf(v, 0.f);
            *p = wmma::__float_to_tf32(v);
        }

        cp_wait<1>();          // Wb[ch] landed (Wa[ch+1] may still be pending)
        __syncthreads();       // rS fully written; bufA free

        if (ch + 1 < nch) {    // prefetch Wb[ch+1] into slot ia (just freed)
            float* nb = WBF + ia * BUF_FLOATS;
            const float* src = Wb + f0 + 64;
            for (int i = tid; i < 128 * 16; i += 512) {
                int d2 = i >> 4, s = i & 15;
                cp16(nb + d2 * LDR + s * 4, src + (size_t)d2 * F + s * 4);
            }
            cp_commit();
        }

        // Stage 2: acc[r0:+16, wc*64:+64] += rS_rows @ WbChunk^T
#pragma unroll
        for (int kk = 0; kk < 8; kk++) {
            wmma::fragment<wmma::matrix_a, 16, 16, 8, wmma::precision::tf32, wmma::row_major> aF;
            wmma::load_matrix_sync(aF, rS + r0 * LDR + kk * 8, LDR);
#pragma unroll
            for (int jj = 0; jj < 4; jj++) {
                wmma::fragment<wmma::matrix_b, 16, 16, 8, wmma::precision::tf32, wmma::col_major> bF;
                wmma::load_matrix_sync(bF, bufB + (wc * 64 + jj * 16) * LDR + kk * 8, LDR);
                wmma::mma_sync(acc[jj], aF, bF, acc[jj]);
            }
        }
        ia = in;
    }

    // Park accumulators in hA (free: all stage-1 reads are past the last mid-chunk sync)
#pragma unroll
    for (int jj = 0; jj < 4; jj++)
        wmma::store_matrix_sync(hA + r0 * LDH + wc * 64 + jj * 16, acc[jj], LDH,
                                wmma::mem_row_major);
    __syncthreads();

    // Epilogue: residual + bias + LayerNorm, warp handles 8 rows
    for (int i = 0; i < 8; i++) {
        int lr = w * 8 + i;
        int gr = row0 + lr;
        if (gr >= N) continue;
        float vals[4];
        float s = 0.f, sq = 0.f;
#pragma unroll
        for (int q = 0; q < 4; q++) {
            int c = lane + q * 32;
            float v = g_h[(size_t)gr * D + c] + hA[lr * LDH + c] + bb[c];
            vals[q] = v;
            s += v; sq += v * v;
        }
#pragma unroll
        for (int o = 16; o; o >>= 1) {
            s  += __shfl_xor_sync(0xffffffffu, s, o);
            sq += __shfl_xor_sync(0xffffffffu, sq, o);
        }
        float m   = s * (1.f / 128.f);
        float var = sq * (1.f / 128.f) - m * m;
        float inv = rsqrtf(var + 1e-5f);
#pragma unroll
        for (int q = 0; q < 4; q++) {
            int c = lane + q * 32;
            g_h[(size_t)gr * D + c] = (vals[q] - m) * inv * lng[c] + lnb[c];
        }
    }
}

// ---------------------------------------------------------------------------
// z = relu(h @ Wd^T + bd) : one warp per row
__global__ void k_head(const float* __restrict__ Wd, const float* __restrict__ bd, int N) {
    int warp = (blockIdx.x * blockDim.x + threadIdx.x) >> 5;
    int lane = threadIdx.x & 31;
    if (warp >= N) return;
    float s = 0.f;
#pragma unroll
    for (int q = 0; q < 4; q++) {
        int c = lane + q * 32;
        s += g_h[(size_t)warp * D + c] * Wd[c];
    }
#pragma unroll
    for (int o = 16; o; o >>= 1) s += __shfl_xor_sync(0xffffffffu, s, o);
    if (lane == 0) g_z[warp] = fmaxf(s + bd[0], 0.f);
}

__global__ void k_deg_init(int N) {
    int n = blockIdx.x * blockDim.x + threadIdx.x;
    if (n < N) g_deg[n] = 1.0f;  // self-loop
}

__global__ void k_deg_count(const int* __restrict__ col, int E) {
    int e = blockIdx.x * blockDim.x + threadIdx.x;
    if (e < E) atomicAdd(&g_deg[col[e]], 1.0f);
}

__global__ void k_dis_u(int N) {
    int n = blockIdx.x * blockDim.x + threadIdx.x;
    if (n >= N) return;
    float dis = rsqrtf(fmaxf(g_deg[n], 1.0f));
    float u = g_z[n] * dis;
    g_dis[n] = dis;
    g_u[n] = u;
    g_t[n] = u;  // self-loop term
}

__global__ void k_scatter(const int* __restrict__ row, const int* __restrict__ col, int E) {
    int e = blockIdx.x * blockDim.x + threadIdx.x;
    if (e < E) atomicAdd(&g_t[col[e]], g_u[row[e]]);
}

// out[n] = sum_k relu(s*Wg[k]+bg[k])*Wf[k] + bf ; s = dis[n]*t[n]
__global__ void k_out(const float* __restrict__ Wg, const float* __restrict__ bg,
                      const float* __restrict__ Wf, const float* __restrict__ bf,
                      float* __restrict__ out, int N) {
    int n = blockIdx.x * blockDim.x + threadIdx.x;
    if (n >= N) return;
    float s = g_dis[n] * g_t[n];
    float a = bf[0];
#pragma unroll
    for (int k = 0; k < 32; k++)
        a += fmaxf(s * Wg[k] + bg[k], 0.f) * Wf[k];
    out[n] = a;
}

// ---------------------------------------------------------------------------
extern "C" void kernel_launch(void* const* d_in, const int* in_sizes, int n_in,
                              void* d_out, int out_size) {
    const float* x    = (const float*)d_in[0];
    const int*   edge = (const int*)  d_in[1];
    const float* Win  = (const float*)d_in[2];
    const float* b_in = (const float*)d_in[3];
    const float* Wv   = (const float*)d_in[4];
    const float* bv   = (const float*)d_in[5];
    const float* Wo   = (const float*)d_in[6];
    const float* bo   = (const float*)d_in[7];
    const float* W1   = (const float*)d_in[8];
    const float* b1   = (const float*)d_in[9];
    const float* W2   = (const float*)d_in[10];
    const float* b2   = (const float*)d_in[11];
    const float* ln1g = (const float*)d_in[12];
    const float* ln1b = (const float*)d_in[13];
    const float* ln2g = (const float*)d_in[14];
    const float* ln2b = (const float*)d_in[15];
    const float* Wd   = (const float*)d_in[16];
    const float* bd   = (const float*)d_in[17];
    const float* Wg   = (const float*)d_in[18];
    const float* bg   = (const float*)d_in[19];
    const float* Wf   = (const float*)d_in[20];
    const float* bf   = (const float*)d_in[21];

    const int N = in_sizes[0] / 3;
    const int E = in_sizes[1] / 2;
    const int F = 2048;

    // tf32-RN pre-converted weight scratch layout
    float* wcvt;
    cudaGetSymbolAddress((void**)&wcvt, g_wcvt);
    const size_t OWV = 0, OWO = 49152, OW1 = 98304, OW2 = 884736;

    cudaFuncSetAttribute(fused_layer_kernel,
                         cudaFuncAttributeMaxDynamicSharedMemorySize, SMEM_BYTES);

    k_cvt<<<(49152 + 255) / 256, 256>>>(Wv, wcvt + OWV, 49152);
    k_cvt<<<(49152 + 255) / 256, 256>>>(Wo, wcvt + OWO, 49152);
    k_cvt<<<(786432 + 255) / 256, 256>>>(W1, wcvt + OW1, 786432);
    k_cvt<<<(786432 + 255) / 256, 256>>>(W2, wcvt + OW2, 786432);

    k_input<<<(N * D + 255) / 256, 256>>>(x, Win, b_in, N);

    const int blocks = (N + 127) / 128;
    for (int i = 0; i < 3; i++) {
        fused_layer_kernel<<<blocks, 512, SMEM_BYTES>>>(
            wcvt + OWV + (size_t)i * D * D, bv + i * D,
            wcvt + OWO + (size_t)i * D * D, bo + i * D,
            ln1g + i * D, ln1b + i * D, /*F=*/D, /*relu_mid=*/0, N);
        fused_layer_kernel<<<blocks, 512, SMEM_BYTES>>>(
            wcvt + OW1 + (size_t)i * F * D, b1 + i * F,
            wcvt + OW2 + (size_t)i * D * F, b2 + i * D,
            ln2g + i * D, ln2b + i * D, /*F=*/F, /*relu_mid=*/1, N);
    }

    k_head<<<(N + 7) / 8, 256>>>(Wd, bd, N);
    k_deg_init<<<(N + 255) / 256, 256>>>(N);
    k_deg_count<<<(E + 255) / 256, 256>>>(edge + E, E);
    k_dis_u<<<(N + 255) / 256, 256>>>(N);
    k_scatter<<<(E + 255) / 256, 256>>>(edge, edge + E, E);
    k_out<<<(N + 255) / 256, 256>>>(Wg, bg, Wf, bf, (float*)d_out, N);
}

// round 5
// speedup vs baseline: 9.8405x; 3.2503x over previous
#include <cuda_runtime.h>
#include <cuda_fp16.h>
#include <mma.h>
#include <cstdint>

using namespace nvcuda;

#define NMAX 200000
#define D 128
#define LDH 136   // hA leading dim (halves)
#define LDR 72    // rS / Wb-slot leading dim (halves)
#define LDF 68    // fS leading dim (floats)  -- 64 cols + 4 pad
#define LDP 132   // park leading dim (floats)

// smem layout in halves:
//  hA:    [128][136] half          @ 0        (17408 h)
//  rS:    [128][72]  half          @ 17408    (9216 h)
//  fS:    [128][68]  float         @ 26624    (17408 h-equiv)
//  slots: 4 x 9216 h               @ 44032
// park (float[128][132]) aliases fS+slots region (offset 26624 h, 33792 h long).
#define HA_OFF 0
#define RS_OFF 17408
#define FS_OFF 26624
#define SL_OFF 44032
#define SL_SZ  9216
static const int SMEM_BYTES = (SL_OFF + 4 * SL_SZ) * 2;  // 161792 B

// Scratch (static device globals: allocation is forbidden)
__device__ float g_h[(size_t)NMAX * D];
__device__ float g_z[NMAX];
__device__ float g_deg[NMAX];
__device__ float g_dis[NMAX];
__device__ float g_u[NMAX];
__device__ float g_t[NMAX];
// fp16 weights: [W1 3x262144 | W2 3x262144 | Wc 3x16384]
__device__ __half g_wh[1622016];
__device__ float g_bc[384];  // fused attn bias, 3 x 128

#define OW1 0
#define OW2 786432
#define OWC 1572864

// ---------------------------------------------------------------------------
__device__ __forceinline__ void cp16h(__half* dst_smem, const __half* src) {
    unsigned int d = (unsigned int)__cvta_generic_to_shared(dst_smem);
    asm volatile("cp.async.cg.shared.global [%0], [%1], 16;\n" :: "r"(d), "l"(src));
}
__device__ __forceinline__ void cp_commit() { asm volatile("cp.async.commit_group;\n"); }
template <int NPEND>
__device__ __forceinline__ void cp_wait() { asm volatile("cp.async.wait_group %0;\n" :: "n"(NPEND)); }

// ---------------------------------------------------------------------------
__global__ void k_cvt_h(const float* __restrict__ src, __half* __restrict__ dst, int n) {
    int i = blockIdx.x * blockDim.x + threadIdx.x;
    if (i < n) dst[i] = __float2half_rn(src[i]);
}

// Wc[l] = Wo[l] @ Wv[l]  (fp32 compute, fp16 store). block=(l*128+o), thread=d
__global__ void k_wc(const float* __restrict__ Wo, const float* __restrict__ Wv) {
    int l = blockIdx.x >> 7, o = blockIdx.x & 127, d = threadIdx.x;
    const float* wo = Wo + (size_t)(l * 128 + o) * 128;
    const float* wv = Wv + (size_t)l * 128 * 128;
    float s = 0.f;
#pragma unroll 8
    for (int k = 0; k < 128; k++) s += wo[k] * wv[k * 128 + d];
    g_wh[OWC + (size_t)(l * 128 + o) * 128 + d] = __float2half_rn(s);
}

// bc[l][o] = Wo[l][o] . bv[l] + bo[l][o]
__global__ void k_bc(const float* __restrict__ Wo, const float* __restrict__ bv,
                     const float* __restrict__ bo) {
    int i = blockIdx.x * blockDim.x + threadIdx.x;  // i = l*128+o, 384 total
    if (i >= 384) return;
    int l = i >> 7;
    const float* wo = Wo + (size_t)i * 128;
    float s = bo[i];
#pragma unroll 8
    for (int k = 0; k < 128; k++) s += wo[k] * bv[l * 128 + k];
    g_bc[i] = s;
}

// h = relu(x @ Win^T + b_in)
__global__ void k_input(const float* __restrict__ x, const float* __restrict__ Win,
                        const float* __restrict__ b_in, int N) {
    int idx = blockIdx.x * blockDim.x + threadIdx.x;
    if (idx >= N * D) return;
    int n = idx >> 7, d = idx & 127;
    float v = b_in[d] + x[n * 3 + 0] * Win[d * 3 + 0]
                      + x[n * 3 + 1] * Win[d * 3 + 1]
                      + x[n * 3 + 2] * Win[d * 3 + 2];
    g_h[idx] = fmaxf(v, 0.f);
}

// ---------------------------------------------------------------------------
// Fused transformer sublayer (fp16 wmma, fp32 accum).
// single==0: h = LN(h + Wb @ relu(Wa @ h + ba) + bb); Wa:[F,128], Wb:[128,F] half.
// single==1: h = LN(h + Wa @ h + bb);  Wa:[128,128] half (precombined attn).
// 512 threads = 16 warps: warp w -> rows (w>>1)*16..+16, col half wc=w&1.
__global__ __launch_bounds__(512, 1)
void fused_layer_kernel(const __half* __restrict__ Wa, const float* __restrict__ ba,
                        const __half* __restrict__ Wb, const float* __restrict__ bb,
                        const float* __restrict__ lng, const float* __restrict__ lnb,
                        int F, int single, int N) {
    extern __shared__ __half smem[];
    __half* hA = smem + HA_OFF;
    __half* rS = smem + RS_OFF;
    float*  fS = (float*)(smem + FS_OFF);
    float*  parkF = (float*)(smem + FS_OFF);

    const int tid  = threadIdx.x;
    const int w    = tid >> 5;
    const int lane = tid & 31;
    const int wr   = w >> 1;
    const int wc   = w & 1;
    const int r0   = wr * 16;
    const int row0 = blockIdx.x * 128;

    typedef wmma::fragment<wmma::matrix_a, 16, 16, 16, __half, wmma::row_major> FragA;
    typedef wmma::fragment<wmma::matrix_b, 16, 16, 16, __half, wmma::col_major> FragB;
    typedef wmma::fragment<wmma::accumulator, 16, 16, 16, float> FragC;

    // ---- initial weight prefetch (one commit group) ----
    if (single) {
        // Wc [128 o][128 d] -> two 64-k slots: slot ch holds cols ch*64..+64
        for (int i = tid; i < 2048; i += 512) {
            int ch = i >> 10, r = (i >> 3) & 127, s = i & 7;
            cp16h(smem + SL_OFF + ch * SL_SZ + r * LDR + s * 8,
                  Wa + (size_t)r * 128 + ch * 64 + s * 8);
        }
    } else {
        // Wa[0]: [64 f][128 d] -> slot0 ; Wb[0]: [128 d2][64 f] -> slot1
        for (int i = tid; i < 1024; i += 512) {
            int r = i >> 4, s = i & 15;
            cp16h(smem + SL_OFF + r * LDH + s * 8, Wa + (size_t)r * 128 + s * 8);
        }
        for (int i = tid; i < 1024; i += 512) {
            int r = i >> 3, s = i & 7;
            cp16h(smem + SL_OFF + SL_SZ + r * LDR + s * 8, Wb + (size_t)r * F + s * 8);
        }
    }
    cp_commit();

    // stage input rows as fp16 (zero-pad past N) while copies fly
    for (int i = tid; i < 128 * 128; i += 512) {
        int r = i >> 7, c = i & 127;
        int gr = row0 + r;
        float v = (gr < N) ? g_h[(size_t)gr * D + c] : 0.f;
        hA[r * LDH + c] = __float2half_rn(v);
    }

    FragC acc[4];
#pragma unroll
    for (int j = 0; j < 4; j++) wmma::fill_fragment(acc[j], 0.f);

    if (single) {
        cp_wait<0>();
        __syncthreads();
#pragma unroll
        for (int ch = 0; ch < 2; ch++) {
            const __half* bufB = smem + SL_OFF + ch * SL_SZ;
#pragma unroll
            for (int kk = 0; kk < 4; kk++) {
                FragA aF;
                wmma::load_matrix_sync(aF, hA + r0 * LDH + ch * 64 + kk * 16, LDH);
#pragma unroll
                for (int jj = 0; jj < 4; jj++) {
                    FragB bF;
                    wmma::load_matrix_sync(bF, bufB + (wc * 64 + jj * 16) * LDR + kk * 16, LDR);
                    wmma::mma_sync(acc[jj], aF, bF, acc[jj]);
                }
            }
        }
    } else {
        const int nch = F >> 6;
        for (int ch = 0; ch < nch; ch++) {
            const int f0 = ch << 6;
            const __half* bufA = smem + SL_OFF + (2 * (ch & 1) + 0) * SL_SZ;
            const __half* bufB = smem + SL_OFF + (2 * (ch & 1) + 1) * SL_SZ;

            cp_wait<0>();
            __syncthreads();   // weights[ch] visible; prev stage2 done (slot + rS WAR safe)

            if (ch + 1 < nch) {  // prefetch chunk ch+1 into the other slot pair
                __half* nA = smem + SL_OFF + (2 * ((ch + 1) & 1) + 0) * SL_SZ;
                __half* nB = smem + SL_OFF + (2 * ((ch + 1) & 1) + 1) * SL_SZ;
                const __half* srcA = Wa + (size_t)(f0 + 64) * 128;
                const __half* srcB = Wb + f0 + 64;
                for (int i = tid; i < 1024; i += 512) {
                    int r = i >> 4, s = i & 15;
                    cp16h(nA + r * LDH + s * 8, srcA + (size_t)r * 128 + s * 8);
                }
                for (int i = tid; i < 1024; i += 512) {
                    int r = i >> 3, s = i & 7;
                    cp16h(nB + r * LDR + s * 8, srcB + (size_t)r * F + s * 8);
                }
                cp_commit();
            } else {
                cp_commit();   // keep group count consistent (empty group)
            }

            // Stage 1: fS[r0:+16, wc*32:+32] = hA_rows @ WaChunk^T (fp32 out)
            {
                FragC rf[2];
#pragma unroll
                for (int j = 0; j < 2; j++) wmma::fill_fragment(rf[j], 0.f);
#pragma unroll
                for (int kk = 0; kk < 8; kk++) {
                    FragA aF;
                    wmma::load_matrix_sync(aF, hA + r0 * LDH + kk * 16, LDH);
#pragma unroll
                    for (int j = 0; j < 2; j++) {
                        FragB bF;
                        wmma::load_matrix_sync(bF, bufA + (wc * 32 + j * 16) * LDH + kk * 16, LDH);
                        wmma::mma_sync(rf[j], aF, bF, rf[j]);
                    }
                }
#pragma unroll
                for (int j = 0; j < 2; j++)
                    wmma::store_matrix_sync(fS + r0 * LDF + wc * 32 + j * 16, rf[j], LDF,
                                            wmma::mem_row_major);
            }
            __syncwarp();
            // bias + relu + fp16 convert into rS (warp-private 16x32 region)
            for (int t = lane; t < 16 * 32; t += 32) {
                int rr = t >> 5, cc = t & 31;
                float v = fS[(r0 + rr) * LDF + wc * 32 + cc] + ba[f0 + wc * 32 + cc];
                rS[(r0 + rr) * LDR + wc * 32 + cc] = __float2half_rn(fmaxf(v, 0.f));
            }
            // pair barrier: both warps of this row-tile must finish rS before stage 2
            asm volatile("bar.sync %0, 64;" :: "r"(1 + wr) : "memory");

            // Stage 2: acc[r0:+16, wc*64:+64] += rS_rows @ WbChunk^T
#pragma unroll
            for (int kk = 0; kk < 4; kk++) {
                FragA aF;
                wmma::load_matrix_sync(aF, rS + r0 * LDR + kk * 16, LDR);
#pragma unroll
                for (int jj = 0; jj < 4; jj++) {
                    FragB bF;
                    wmma::load_matrix_sync(bF, bufB + (wc * 64 + jj * 16) * LDR + kk * 16, LDR);
                    wmma::mma_sync(acc[jj], aF, bF, acc[jj]);
                }
            }
        }
    }

    __syncthreads();   // all stage2 reads done; park area (aliases fS+slots) free
#pragma unroll
    for (int jj = 0; jj < 4; jj++)
        wmma::store_matrix_sync(parkF + r0 * LDP + wc * 64 + jj * 16, acc[jj], LDP,
                                wmma::mem_row_major);
    __syncthreads();

    // Epilogue: residual + bias + LayerNorm; warp handles 8 rows
    for (int i = 0; i < 8; i++) {
        int lr = w * 8 + i;
        int gr = row0 + lr;
        if (gr >= N) continue;
        float vals[4];
        float s = 0.f, sq = 0.f;
#pragma unroll
        for (int q = 0; q < 4; q++) {
            int c = lane + q * 32;
            float v = g_h[(size_t)gr * D + c] + parkF[lr * LDP + c] + bb[c];
            vals[q] = v;
            s += v; sq += v * v;
        }
#pragma unroll
        for (int o = 16; o; o >>= 1) {
            s  += __shfl_xor_sync(0xffffffffu, s, o);
            sq += __shfl_xor_sync(0xffffffffu, sq, o);
        }
        float m   = s * (1.f / 128.f);
        float var = sq * (1.f / 128.f) - m * m;
        float inv = rsqrtf(var + 1e-5f);
#pragma unroll
        for (int q = 0; q < 4; q++) {
            int c = lane + q * 32;
            g_h[(size_t)gr * D + c] = (vals[q] - m) * inv * lng[c] + lnb[c];
        }
    }
}

// ---------------------------------------------------------------------------
// z = relu(h @ Wd^T + bd) : one warp per row
__global__ void k_head(const float* __restrict__ Wd, const float* __restrict__ bd, int N) {
    int warp = (blockIdx.x * blockDim.x + threadIdx.x) >> 5;
    int lane = threadIdx.x & 31;
    if (warp >= N) return;
    float s = 0.f;
#pragma unroll
    for (int q = 0; q < 4; q++) {
        int c = lane + q * 32;
        s += g_h[(size_t)warp * D + c] * Wd[c];
    }
#pragma unroll
    for (int o = 16; o; o >>= 1) s += __shfl_xor_sync(0xffffffffu, s, o);
    if (lane == 0) g_z[warp] = fmaxf(s + bd[0], 0.f);
}

__global__ void k_deg_init(int N) {
    int n = blockIdx.x * blockDim.x + threadIdx.x;
    if (n < N) g_deg[n] = 1.0f;  // self-loop
}

__global__ void k_deg_count(const int* __restrict__ col, int E) {
    int e = blockIdx.x * blockDim.x + threadIdx.x;
    if (e < E) atomicAdd(&g_deg[col[e]], 1.0f);
}

__global__ void k_dis_u(int N) {
    int n = blockIdx.x * blockDim.x + threadIdx.x;
    if (n >= N) return;
    float dis = rsqrtf(fmaxf(g_deg[n], 1.0f));
    float u = g_z[n] * dis;
    g_dis[n] = dis;
    g_u[n] = u;
    g_t[n] = u;  // self-loop term
}

__global__ void k_scatter(const int* __restrict__ row, const int* __restrict__ col, int E) {
    int e = blockIdx.x * blockDim.x + threadIdx.x;
    if (e < E) atomicAdd(&g_t[col[e]], g_u[row[e]]);
}

// out[n] = sum_k relu(s*Wg[k]+bg[k])*Wf[k] + bf ; s = dis[n]*t[n]
__global__ void k_out(const float* __restrict__ Wg, const float* __restrict__ bg,
                      const float* __restrict__ Wf, const float* __restrict__ bf,
                      float* __restrict__ out, int N) {
    int n = blockIdx.x * blockDim.x + threadIdx.x;
    if (n >= N) return;
    float s = g_dis[n] * g_t[n];
    float a = bf[0];
#pragma unroll
    for (int k = 0; k < 32; k++)
        a += fmaxf(s * Wg[k] + bg[k], 0.f) * Wf[k];
    out[n] = a;
}

// ---------------------------------------------------------------------------
extern "C" void kernel_launch(void* const* d_in, const int* in_sizes, int n_in,
                              void* d_out, int out_size) {
    const float* x    = (const float*)d_in[0];
    const int*   edge = (const int*)  d_in[1];
    const float* Win  = (const float*)d_in[2];
    const float* b_in = (const float*)d_in[3];
    const float* Wv   = (const float*)d_in[4];
    const float* bv   = (const float*)d_in[5];
    const float* Wo   = (const float*)d_in[6];
    const float* bo   = (const float*)d_in[7];
    const float* W1   = (const float*)d_in[8];
    const float* b1   = (const float*)d_in[9];
    const float* W2   = (const float*)d_in[10];
    const float* b2   = (const float*)d_in[11];
    const float* ln1g = (const float*)d_in[12];
    const float* ln1b = (const float*)d_in[13];
    const float* ln2g = (const float*)d_in[14];
    const float* ln2b = (const float*)d_in[15];
    const float* Wd   = (const float*)d_in[16];
    const float* bd   = (const float*)d_in[17];
    const float* Wg   = (const float*)d_in[18];
    const float* bg   = (const float*)d_in[19];
    const float* Wf   = (const float*)d_in[20];
    const float* bf   = (const float*)d_in[21];

    const int N = in_sizes[0] / 3;
    const int E = in_sizes[1] / 2;
    const int F = 2048;

    __half* wh;
    cudaGetSymbolAddress((void**)&wh, g_wh);
    float* bc;
    cudaGetSymbolAddress((void**)&bc, g_bc);

    cudaFuncSetAttribute(fused_layer_kernel,
                         cudaFuncAttributeMaxDynamicSharedMemorySize, SMEM_BYTES);

    k_cvt_h<<<(786432 + 255) / 256, 256>>>(W1, wh + OW1, 786432);
    k_cvt_h<<<(786432 + 255) / 256, 256>>>(W2, wh + OW2, 786432);
    k_wc<<<384, 128>>>(Wo, Wv);
    k_bc<<<2, 256>>>(Wo, bv, bo);

    k_input<<<(N * D + 255) / 256, 256>>>(x, Win, b_in, N);

    const int blocks = (N + 127) / 128;
    for (int i = 0; i < 3; i++) {
        fused_layer_kernel<<<blocks, 512, SMEM_BYTES>>>(
            wh + OWC + (size_t)i * 16384, nullptr, nullptr,
            bc + i * 128, ln1g + i * D, ln1b + i * D,
            /*F=*/128, /*single=*/1, N);
        fused_layer_kernel<<<blocks, 512, SMEM_BYTES>>>(
            wh + OW1 + (size_t)i * F * D, b1 + i * F,
            wh + OW2 + (size_t)i * D * F, b2 + i * D,
            ln2g + i * D, ln2b + i * D, /*F=*/F, /*single=*/0, N);
    }

    k_head<<<(N + 7) / 8, 256>>>(Wd, bd, N);
    k_deg_init<<<(N + 255) / 256, 256>>>(N);
    k_deg_count<<<(E + 255) / 256, 256>>>(edge + E, E);
    k_dis_u<<<(N + 255) / 256, 256>>>(N);
    k_scatter<<<(E + 255) / 256, 256>>>(edge, edge + E, E);
    k_out<<<(N + 255) / 256, 256>>>(Wg, bg, Wf, bf, (float*)d_out, N);
}